// round 12
// baseline (speedup 1.0000x reference)
#include <cuda_runtime.h>
#include <cuda_fp16.h>
#include <math.h>
#include <stdint.h>

#define NN 50000
#define NE 800000
#define ET (NE + NN)          // edges + self loops
#define D 128
#define H 4
#define HD 32
#define NEG 0.2f
#define NB 49                 // cdiv(NN, 1024) scan blocks
#define ST 3                  // cp.async pipeline stages
#define SUB 8                 // edges per sub-chunk

// ---------------- scratch (static device globals; no allocation) ----------------
__device__ __half g_hh[NN * D];     // layer input features (fp16)
__device__ __half g_xwh[NN * D];    // GCN x@W * dinv[row]  (fp16, gathered)
__device__ float  g_hgcn[NN * D];   // GCN layer output (fp32, residual)
__device__ __half g_hgcnh[NN * D];  // GCN layer output (fp16, GEMM input)
__device__ __half g_xw2h[NN * D];   // GAT x@W  (fp16, gathered)
__device__ float  g_dinv[NN];
__device__ float  g_asrc[NN * H];
__device__ float  g_adst[NN * H];
__device__ int    g_degi[NN];       // zero at entry of every launch (finalize restores)
__device__ int    g_rowptr[NN + 1];
__device__ int    g_cursor[NN];
__device__ int    g_csrc[ET];
__device__ int    g_bsum[NB];

static inline int cdiv(int a, int b) { return (a + b - 1) / b; }

__device__ __forceinline__ uint32_t s2u(const void* p) {
    return (uint32_t)__cvta_generic_to_shared(p);
}

// ---------------- CSR build ----------------
__global__ void k_deg(const int* __restrict__ ei) {
    int e = blockIdx.x * blockDim.x + threadIdx.x;
    if (e >= ET) return;
    int dst = (e < NE) ? ei[NE + e] : (e - NE);
    atomicAdd(&g_degi[dst], 1);
}

__global__ void k_blockscan() {
    __shared__ int wsum[8];
    const int tid = threadIdx.x;
    const int lane = tid & 31, w = tid >> 5;
    const int base = blockIdx.x * 1024 + tid * 4;
    int v[4];
    int s = 0;
#pragma unroll
    for (int j = 0; j < 4; j++) {
        v[j] = (base + j < NN) ? g_degi[base + j] : 0;
        s += v[j];
    }
    int sc = s;
#pragma unroll
    for (int o = 1; o < 32; o <<= 1) {
        int t = __shfl_up_sync(0xffffffffu, sc, o);
        if (lane >= o) sc += t;
    }
    if (lane == 31) wsum[w] = sc;
    __syncthreads();
    if (w == 0) {
        int ws = (lane < 8) ? wsum[lane] : 0;
#pragma unroll
        for (int o = 1; o < 8; o <<= 1) {
            int t = __shfl_up_sync(0xffffffffu, ws, o);
            if (lane >= o) ws += t;
        }
        if (lane < 8) wsum[lane] = ws;
    }
    __syncthreads();
    int run = sc - s + (w ? wsum[w - 1] : 0);
#pragma unroll
    for (int j = 0; j < 4; j++) {
        run += v[j];
        if (base + j < NN) g_rowptr[base + j + 1] = run;
    }
    if (tid == 255) g_bsum[blockIdx.x] = run;
}

__global__ void k_finalize() {
    __shared__ int s_off;
    const int tid = threadIdx.x;
    const int seg = blockIdx.x >> 2;
    if (tid < 32) {
        int acc = 0;
        for (int j = tid; j < seg; j += 32) acc += g_bsum[j];
#pragma unroll
        for (int o = 16; o; o >>= 1) acc += __shfl_xor_sync(0xffffffffu, acc, o);
        if (tid == 0) s_off = acc;
    }
    __syncthreads();
    int i = blockIdx.x * 256 + tid;
    if (i >= NN) return;
    int deg = g_degi[i];
    g_degi[i] = 0;
    int r = g_rowptr[i + 1] + s_off;
    g_rowptr[i + 1] = r;
    g_cursor[i] = r - deg;
    g_dinv[i] = rsqrtf((float)deg);
    if (i == 0) g_rowptr[0] = 0;
}

__global__ void k_fill(const int* __restrict__ ei) {
    int e = blockIdx.x * blockDim.x + threadIdx.x;
    if (e >= ET) return;
    int src = (e < NE) ? ei[e]      : (e - NE);
    int dst = (e < NE) ? ei[NE + e] : (e - NE);
    int pos = atomicAdd(&g_cursor[dst], 1);
    g_csrc[pos] = src;
}

// ---------------- fp32 -> fp16 conversion ----------
__global__ void k_h2h(const float* __restrict__ x) {
    int i = blockIdx.x * blockDim.x + threadIdx.x;
    if (i >= NN * D / 8) return;
    float4 a = ((const float4*)x)[2 * i], b = ((const float4*)x)[2 * i + 1];
    uint4 v;
    *(__half2*)&v.x = __floats2half2_rn(a.x, a.y);
    *(__half2*)&v.y = __floats2half2_rn(a.z, a.w);
    *(__half2*)&v.z = __floats2half2_rn(b.x, b.y);
    *(__half2*)&v.w = __floats2half2_rn(b.z, b.w);
    ((uint4*)g_hh)[i] = v;
}

// ---------------- fp16 tensor-core GEMM (unchanged from R10) ----------
__device__ __forceinline__ void mma_f16(float* c, const uint32_t* a, const uint32_t* b) {
    asm volatile(
        "mma.sync.aligned.m16n8k16.row.col.f32.f16.f16.f32 "
        "{%0,%1,%2,%3}, {%4,%5,%6,%7}, {%8,%9}, {%0,%1,%2,%3};"
        : "+f"(c[0]), "+f"(c[1]), "+f"(c[2]), "+f"(c[3])
        : "r"(a[0]), "r"(a[1]), "r"(a[2]), "r"(a[3]), "r"(b[0]), "r"(b[1]));
}

__device__ __forceinline__ void gemm_gload(const __half* __restrict__ A,
                                           const float* __restrict__ W,
                                           int M, int m0, int tid, int k0,
                                           uint4* ra, float4* rb) {
    int row = tid >> 1;
    int k8 = (tid & 1) * 8;
    uint4 v = make_uint4(0u, 0u, 0u, 0u);
    if (m0 + row < M) v = *(const uint4*)&A[(size_t)(m0 + row) * D + k0 + k8];
    *ra = v;
#pragma unroll
    for (int i = 0; i < 2; i++) {
        int f = tid * 2 + i;
        int kl = f >> 5;
        int n4 = (f & 31) * 4;
        rb[i] = *(const float4*)&W[(size_t)(k0 + kl) * D + n4];
    }
}

__device__ __forceinline__ void gemm_sstore(uint32_t (&As)[8][32][4],
                                            uint32_t (&Bs)[16][32][2],
                                            const uint4& ra, const float4* rb, int tid) {
    int row = tid >> 1;
    int k8 = (tid & 1) * 8;
    int mt = row >> 4, mr = row & 15;
    const uint32_t av[4] = {ra.x, ra.y, ra.z, ra.w};
#pragma unroll
    for (int jj = 0; jj < 4; jj++) {
        int kk = k8 + jj * 2;
        As[mt][(mr & 7) * 4 + ((kk & 7) >> 1)][(mr >> 3) | ((kk >> 3) << 1)] = av[jj];
    }
#pragma unroll
    for (int i = 0; i < 2; i++) {
        int f = tid * 2 + i;
        int kk = f >> 5;
        int n4 = (f & 31) * 4;
        float ww[4] = {rb[i].x, rb[i].y, rb[i].z, rb[i].w};
#pragma unroll
        for (int j = 0; j < 4; j++) {
            int n = n4 + j;
            __half* hp = (__half*)&Bs[n >> 3][(n & 7) * 4 + ((kk & 7) >> 1)][kk >> 3];
            hp[kk & 1] = __float2half_rn(ww[j]);
        }
    }
}

__global__ void __launch_bounds__(256) k_gemm(const __half* __restrict__ A,
                                              const float* __restrict__ W,
                                              __half* __restrict__ C, int M,
                                              const float* __restrict__ rowscale,
                                              const float* __restrict__ ws,
                                              const float* __restrict__ wd) {
    __shared__ uint32_t As[2][8][32][4];
    __shared__ uint32_t Bs[2][16][32][2];
    const int tid = threadIdx.x;
    const int lane = tid & 31;
    const int warp = tid >> 5;
    const int wm = warp >> 1;
    const int wn = warp & 1;
    const int m0 = blockIdx.x * 128;

    float acc[2][8][4];
#pragma unroll
    for (int i = 0; i < 2; i++)
#pragma unroll
        for (int j = 0; j < 8; j++)
#pragma unroll
            for (int q = 0; q < 4; q++) acc[i][j][q] = 0.f;

    uint4 ra; float4 rb[2];
    gemm_gload(A, W, M, m0, tid, 0, &ra, rb);
    gemm_sstore(As[0], Bs[0], ra, rb, tid);
    __syncthreads();
    int buf = 0;

    for (int k0 = 0; k0 < 128; k0 += 16) {
        const bool more = (k0 + 16 < 128);
        if (more) gemm_gload(A, W, M, m0, tid, k0 + 16, &ra, rb);
        uint32_t afr[2][4];
#pragma unroll
        for (int mf = 0; mf < 2; mf++) {
            uint4 t = *(const uint4*)&As[buf][wm * 2 + mf][lane][0];
            afr[mf][0] = t.x; afr[mf][1] = t.y; afr[mf][2] = t.z; afr[mf][3] = t.w;
        }
        uint32_t bfr[8][2];
#pragma unroll
        for (int nf = 0; nf < 8; nf++) {
            uint2 t = *(const uint2*)&Bs[buf][wn * 8 + nf][lane][0];
            bfr[nf][0] = t.x; bfr[nf][1] = t.y;
        }
#pragma unroll
        for (int mf = 0; mf < 2; mf++)
#pragma unroll
            for (int nf = 0; nf < 8; nf++)
                mma_f16(acc[mf][nf], afr[mf], bfr[nf]);
        if (more) {
            gemm_sstore(As[buf ^ 1], Bs[buf ^ 1], ra, rb, tid);
            __syncthreads();
            buf ^= 1;
        }
    }

    const int g = lane >> 2, q = lane & 3;
#pragma unroll
    for (int mf = 0; mf < 2; mf++) {
        int row0 = m0 + wm * 32 + mf * 16 + g;
        int row1 = row0 + 8;
        float s0 = 1.f, s1 = 1.f;
        if (rowscale) {
            if (row0 < M) s0 = rowscale[row0];
            if (row1 < M) s1 = rowscale[row1];
        }
#pragma unroll
        for (int nf = 0; nf < 8; nf++) {
            int colh = wn * 32 + nf * 4 + q;
            if (row0 < M)
                ((__half2*)C)[(size_t)row0 * 64 + colh] =
                    __floats2half2_rn(acc[mf][nf][0] * s0, acc[mf][nf][1] * s0);
            if (row1 < M)
                ((__half2*)C)[(size_t)row1 * 64 + colh] =
                    __floats2half2_rn(acc[mf][nf][2] * s1, acc[mf][nf][3] * s1);
        }
    }

    if (ws) {
        const int h0 = 2 * wn, h1 = 2 * wn + 1;
#pragma unroll
        for (int mf = 0; mf < 2; mf++) {
            int row0 = m0 + wm * 32 + mf * 16 + g;
            int row1 = row0 + 8;
            float sA0 = 0.f, dA0 = 0.f, sB0 = 0.f, dB0 = 0.f;
            float sA1 = 0.f, dA1 = 0.f, sB1 = 0.f, dB1 = 0.f;
#pragma unroll
            for (int nf = 0; nf < 8; nf++) {
                int col = (nf & 3) * 8 + q * 2;
                int h = (nf < 4) ? h0 : h1;
                float w0 = ws[h * HD + col], w1 = ws[h * HD + col + 1];
                float e0 = wd[h * HD + col], e1 = wd[h * HD + col + 1];
                float p0 = acc[mf][nf][0] * w0 + acc[mf][nf][1] * w1;
                float p1 = acc[mf][nf][0] * e0 + acc[mf][nf][1] * e1;
                float p2 = acc[mf][nf][2] * w0 + acc[mf][nf][3] * w1;
                float p3 = acc[mf][nf][2] * e0 + acc[mf][nf][3] * e1;
                if (nf < 4) { sA0 += p0; dA0 += p1; sA1 += p2; dA1 += p3; }
                else        { sB0 += p0; dB0 += p1; sB1 += p2; dB1 += p3; }
            }
#pragma unroll
            for (int o = 1; o <= 2; o <<= 1) {
                sA0 += __shfl_xor_sync(0xffffffffu, sA0, o);
                dA0 += __shfl_xor_sync(0xffffffffu, dA0, o);
                sB0 += __shfl_xor_sync(0xffffffffu, sB0, o);
                dB0 += __shfl_xor_sync(0xffffffffu, dB0, o);
                sA1 += __shfl_xor_sync(0xffffffffu, sA1, o);
                dA1 += __shfl_xor_sync(0xffffffffu, dA1, o);
                sB1 += __shfl_xor_sync(0xffffffffu, sB1, o);
                dB1 += __shfl_xor_sync(0xffffffffu, dB1, o);
            }
            if (q == 0) {
                if (row0 < M) {
                    g_asrc[row0 * H + h0] = sA0; g_adst[row0 * H + h0] = dA0;
                    g_asrc[row0 * H + h1] = sB0; g_adst[row0 * H + h1] = dB0;
                }
                if (row1 < M) {
                    g_asrc[row1 * H + h0] = sA1; g_adst[row1 * H + h0] = dA1;
                    g_asrc[row1 * H + h1] = sB1; g_adst[row1 * H + h1] = dB1;
                }
            }
        }
    }
}

// ---------------- cp.async helpers for pipelined gather ----------
// Stage one SUB(8)-edge sub-chunk of 256B feature rows into smem.
__device__ __forceinline__ void issue8(unsigned char* stage_slot,
                                       const __half* __restrict__ feat,
                                       const int* s_src_w, int e0, int cnt, int lane) {
    int sub = lane >> 4;   // which edge of the pair this round
    int seg = lane & 15;   // 16B segment within the 256B row
#pragma unroll
    for (int r = 0; r < 4; r++) {
        int el = r * 2 + sub;          // 0..7 local edge
        int e = e0 + el;
        if (e < cnt) {
            int src = s_src_w[e];
            const void* gp = (const char*)(feat + (size_t)src * D) + seg * 16;
            uint32_t sp = s2u(stage_slot + el * 256 + seg * 16);
            asm volatile("cp.async.cg.shared.global [%0], [%1], 16;" :: "r"(sp), "l"(gp));
        }
    }
    asm volatile("cp.async.commit_group;" ::: "memory");
}

__device__ __forceinline__ void wait_pending(int pend) {
    if (pend <= 0)      asm volatile("cp.async.wait_group 0;" ::: "memory");
    else if (pend == 1) asm volatile("cp.async.wait_group 1;" ::: "memory");
    else                asm volatile("cp.async.wait_group 2;" ::: "memory");
}

// ---------------- GCN aggregation (warp per dst, cp.async pipelined) ----------
// xwh pre-scaled by dinv[src]; out = (sum xwh[src]) * dinv[dst] + bias.
__global__ void __launch_bounds__(128) k_gcn_agg(const float* __restrict__ b) {
    __shared__ int s_src[4][32];
    __shared__ __align__(16) unsigned char stage[4][ST][SUB * 256];
    int gt = blockIdx.x * blockDim.x + threadIdx.x;
    int n = gt >> 5, lane = gt & 31, w = threadIdx.x >> 5;
    if (n >= NN) return;
    const int start = g_rowptr[n], end = g_rowptr[n + 1];
    float4 acc = make_float4(0.f, 0.f, 0.f, 0.f);
    for (int j0 = start; j0 < end; j0 += 32) {
        int jj = j0 + lane;
        if (jj < end) s_src[w][lane] = g_csrc[jj];
        __syncwarp();
        int cnt = min(32, end - j0);
        int nsub = (cnt + SUB - 1) / SUB;
        int issued = 0;
        for (; issued < nsub && issued < ST; issued++)
            issue8(stage[w][issued], g_xwh, s_src[w], issued * SUB, cnt, lane);
        for (int s = 0; s < nsub; s++) {
            wait_pending(issued - s - 1);
            __syncwarp();
            unsigned char* slot = stage[w][s % ST];
#pragma unroll
            for (int el = 0; el < SUB; el++) {
                int e = s * SUB + el;
                if (e >= cnt) break;
                uint2 u = *(const uint2*)(slot + el * 256 + lane * 8);
                float2 f0 = __half22float2(*(__half2*)&u.x);
                float2 f1 = __half22float2(*(__half2*)&u.y);
                acc.x += f0.x; acc.y += f0.y; acc.z += f1.x; acc.w += f1.y;
            }
            __syncwarp();
            if (issued < nsub) {
                issue8(stage[w][issued % ST], g_xwh, s_src[w], issued * SUB, cnt, lane);
                issued++;
            }
        }
        __syncwarp();
    }
    const float din = g_dinv[n];
    float4 bb = ((const float4*)b)[lane];
    float4 o;
    o.x = fmaf(acc.x, din, bb.x);
    o.y = fmaf(acc.y, din, bb.y);
    o.z = fmaf(acc.z, din, bb.z);
    o.w = fmaf(acc.w, din, bb.w);
    ((float4*)g_hgcn)[n * 32 + lane] = o;
    uint2 hv;
    *(__half2*)&hv.x = __floats2half2_rn(o.x, o.y);
    *(__half2*)&hv.y = __floats2half2_rn(o.z, o.w);
    ((uint2*)g_hgcnh)[n * 32 + lane] = hv;
}

__device__ __forceinline__ float lrelu(float v) { return (v > 0.f) ? v : NEG * v; }

// ---------------- GAT + residual + LayerNorm + ReLU (warp per dst, pipelined) --
__global__ void __launch_bounds__(128) k_gat_ln(const float* __restrict__ gb,
                                                const float* __restrict__ lg,
                                                const float* __restrict__ lb,
                                                float* __restrict__ outf,
                                                __half* __restrict__ outh) {
    __shared__ int    s_src[4][32];
    __shared__ float4 s_al[4][32];
    __shared__ __align__(16) unsigned char stage[4][ST][SUB * 256];
    int gt = blockIdx.x * blockDim.x + threadIdx.x;
    int n = gt >> 5, lane = gt & 31, w = threadIdx.x >> 5;
    if (n >= NN) return;
    const int start = g_rowptr[n], end = g_rowptr[n + 1];
    const float4 ad = ((const float4*)g_adst)[n];

    // phase A: z per head
    float z0 = 0.f, z1 = 0.f, z2 = 0.f, z3 = 0.f;
    for (int j = start + lane; j < end; j += 32) {
        int src = g_csrc[j];
        float4 as = ((const float4*)g_asrc)[src];
        z0 += __expf(lrelu(as.x + ad.x));
        z1 += __expf(lrelu(as.y + ad.y));
        z2 += __expf(lrelu(as.z + ad.z));
        z3 += __expf(lrelu(as.w + ad.w));
    }
#pragma unroll
    for (int o = 16; o; o >>= 1) {
        z0 += __shfl_xor_sync(0xffffffffu, z0, o);
        z1 += __shfl_xor_sync(0xffffffffu, z1, o);
        z2 += __shfl_xor_sync(0xffffffffu, z2, o);
        z3 += __shfl_xor_sync(0xffffffffu, z3, o);
    }
    const float r0 = 1.f / z0, r1 = 1.f / z1, r2 = 1.f / z2, r3 = 1.f / z3;

    // phase B: weighted gather, cp.async pipelined
    float4 acc = ((const float4*)gb)[lane];
    const int hsel = lane >> 3;
    for (int j0 = start; j0 < end; j0 += 32) {
        int jj = j0 + lane;
        if (jj < end) {
            int src = g_csrc[jj];
            float4 as = ((const float4*)g_asrc)[src];
            float4 al;
            al.x = __expf(lrelu(as.x + ad.x)) * r0;
            al.y = __expf(lrelu(as.y + ad.y)) * r1;
            al.z = __expf(lrelu(as.z + ad.z)) * r2;
            al.w = __expf(lrelu(as.w + ad.w)) * r3;
            s_src[w][lane] = src;
            s_al[w][lane] = al;
        }
        __syncwarp();
        int cnt = min(32, end - j0);
        int nsub = (cnt + SUB - 1) / SUB;
        int issued = 0;
        for (; issued < nsub && issued < ST; issued++)
            issue8(stage[w][issued], g_xw2h, s_src[w], issued * SUB, cnt, lane);
        for (int s = 0; s < nsub; s++) {
            wait_pending(issued - s - 1);
            __syncwarp();
            unsigned char* slot = stage[w][s % ST];
#pragma unroll
            for (int el = 0; el < SUB; el++) {
                int e = s * SUB + el;
                if (e >= cnt) break;
                float a = ((const float*)&s_al[w][e])[hsel];
                uint2 u = *(const uint2*)(slot + el * 256 + lane * 8);
                float2 f0 = __half22float2(*(__half2*)&u.x);
                float2 f1 = __half22float2(*(__half2*)&u.y);
                acc.x = fmaf(f0.x, a, acc.x);
                acc.y = fmaf(f0.y, a, acc.y);
                acc.z = fmaf(f1.x, a, acc.z);
                acc.w = fmaf(f1.y, a, acc.w);
            }
            __syncwarp();
            if (issued < nsub) {
                issue8(stage[w][issued % ST], g_xw2h, s_src[w], issued * SUB, cnt, lane);
                issued++;
            }
        }
        __syncwarp();
    }

    // residual + LayerNorm + ReLU
    float4 c = ((const float4*)g_hgcn)[n * 32 + lane];
    acc.x += c.x; acc.y += c.y; acc.z += c.z; acc.w += c.w;
    float s = acc.x + acc.y + acc.z + acc.w;
#pragma unroll
    for (int o = 16; o; o >>= 1) s += __shfl_xor_sync(0xffffffffu, s, o);
    float mu = s * (1.0f / D);
    float dx = acc.x - mu, dy = acc.y - mu, dz = acc.z - mu, dw = acc.w - mu;
    float q = dx * dx + dy * dy + dz * dz + dw * dw;
#pragma unroll
    for (int o = 16; o; o >>= 1) q += __shfl_xor_sync(0xffffffffu, q, o);
    float rs = rsqrtf(q * (1.0f / D) + 1e-5f);
    float4 gg = ((const float4*)lg)[lane];
    float4 bb = ((const float4*)lb)[lane];
    float4 y;
    y.x = fmaxf(dx * rs * gg.x + bb.x, 0.f);
    y.y = fmaxf(dy * rs * gg.y + bb.y, 0.f);
    y.z = fmaxf(dz * rs * gg.z + bb.z, 0.f);
    y.w = fmaxf(dw * rs * gg.w + bb.w, 0.f);
    if (outf) {
        ((float4*)outf)[n * 32 + lane] = y;
    } else {
        uint2 hv;
        *(__half2*)&hv.x = __floats2half2_rn(y.x, y.y);
        *(__half2*)&hv.y = __floats2half2_rn(y.z, y.w);
        ((uint2*)outh)[n * 32 + lane] = hv;
    }
}

// ---------------- launch ----------------
extern "C" void kernel_launch(void* const* d_in, const int* in_sizes, int n_in,
                              void* d_out, int out_size) {
    const float* x      = (const float*)d_in[0];
    const int*   ei     = (const int*)  d_in[1];
    const float* gcn_w  = (const float*)d_in[2];
    const float* gcn_b  = (const float*)d_in[3];
    const float* gat_w  = (const float*)d_in[4];
    const float* att_s  = (const float*)d_in[5];
    const float* att_d  = (const float*)d_in[6];
    const float* gat_b  = (const float*)d_in[7];
    const float* ln_g   = (const float*)d_in[8];
    const float* ln_b   = (const float*)d_in[9];
    float* out = (float*)d_out;

    float  *p_dinv;
    __half *p_hh, *p_hgcnh, *p_xwh, *p_xw2h;
    cudaGetSymbolAddress((void**)&p_dinv,   g_dinv);
    cudaGetSymbolAddress((void**)&p_hh,     g_hh);
    cudaGetSymbolAddress((void**)&p_hgcnh,  g_hgcnh);
    cudaGetSymbolAddress((void**)&p_xwh,    g_xwh);
    cudaGetSymbolAddress((void**)&p_xw2h,   g_xw2h);

    const int T = 256;
    const int TG = 128;   // gather kernels: 4 warps per block
    // CSR build (per replay; graph-capturable, no allocation).
    k_deg<<<cdiv(ET, T), T>>>(ei);
    k_blockscan<<<NB, 256>>>();
    k_finalize<<<cdiv(NN, T), T>>>();
    k_fill<<<cdiv(ET, T), T>>>(ei);
    // x -> fp16
    k_h2h<<<cdiv(NN * D / 8, T), T>>>(x);

    for (int l = 0; l < 3; l++) {
        // GCN (output pre-scaled by dinv[row])
        k_gemm<<<cdiv(NN, 128), T>>>(p_hh, gcn_w + l * D * D, p_xwh, NN, p_dinv,
                                     nullptr, nullptr);
        k_gcn_agg<<<cdiv(NN * 32, TG), TG>>>(gcn_b + l * D);
        // GAT (fused attention coefficients in epilogue)
        k_gemm<<<cdiv(NN, 128), T>>>(p_hgcnh, gat_w + l * D * D, p_xw2h, NN, nullptr,
                                     att_s + l * H * HD, att_d + l * H * HD);
        // GAT aggregation + residual + LN + ReLU fused
        if (l == 2)
            k_gat_ln<<<cdiv(NN * 32, TG), TG>>>(gat_b + l * D, ln_g + l * D, ln_b + l * D,
                                                out, nullptr);
        else
            k_gat_ln<<<cdiv(NN * 32, TG), TG>>>(gat_b + l * D, ln_g + l * D, ln_b + l * D,
                                                nullptr, p_hh);
    }
}

// round 13
// speedup vs baseline: 1.2175x; 1.2175x over previous
#include <cuda_runtime.h>
#include <cuda_fp16.h>
#include <math.h>
#include <stdint.h>

#define NN 50000
#define NE 800000
#define ET (NE + NN)          // edges + self loops
#define D 128
#define H 4
#define HD 32
#define NEG 0.2f
#define NB 49                 // cdiv(NN, 1024) scan blocks
#define ETH ((ET + 1) / 2)    // half split for ILP-2 edge kernels

// ---------------- scratch (static device globals; no allocation) ----------------
__device__ __half g_hh[NN * D];     // layer input features (fp16)
__device__ __half g_xwh[NN * D];    // GCN x@W * dinv[row]  (fp16, gathered)
__device__ float  g_hgcn[NN * D];   // GCN layer output (fp32, residual)
__device__ __half g_hgcnh[NN * D];  // GCN layer output (fp16, GEMM input)
__device__ __half g_xw2h[NN * D];   // GAT x@W  (fp16, gathered)
__device__ float  g_dinv[NN];
__device__ float  g_asrc[NN * H];
__device__ float  g_adst[NN * H];
__device__ int    g_degi[NN];       // zero at entry of every launch (finalize restores)
__device__ int    g_rowptr[NN + 1];
__device__ int    g_cursor[NN];
__device__ int    g_csrc[ET];
__device__ int    g_bsum[NB];

static inline int cdiv(int a, int b) { return (a + b - 1) / b; }

// ---------------- CSR build (ILP-2: two independent atomics per thread) --------
__global__ void k_deg(const int* __restrict__ ei) {
    int e = blockIdx.x * blockDim.x + threadIdx.x;
    if (e >= ETH) return;
    int d0 = (e < NE) ? ei[NE + e] : (e - NE);
    atomicAdd(&g_degi[d0], 1);
    int e2 = e + ETH;
    if (e2 < ET) {
        int d1 = (e2 < NE) ? ei[NE + e2] : (e2 - NE);
        atomicAdd(&g_degi[d1], 1);
    }
}

__global__ void k_blockscan() {
    __shared__ int wsum[8];
    const int tid = threadIdx.x;
    const int lane = tid & 31, w = tid >> 5;
    const int base = blockIdx.x * 1024 + tid * 4;
    int v[4];
    int s = 0;
#pragma unroll
    for (int j = 0; j < 4; j++) {
        v[j] = (base + j < NN) ? g_degi[base + j] : 0;
        s += v[j];
    }
    int sc = s;
#pragma unroll
    for (int o = 1; o < 32; o <<= 1) {
        int t = __shfl_up_sync(0xffffffffu, sc, o);
        if (lane >= o) sc += t;
    }
    if (lane == 31) wsum[w] = sc;
    __syncthreads();
    if (w == 0) {
        int ws = (lane < 8) ? wsum[lane] : 0;
#pragma unroll
        for (int o = 1; o < 8; o <<= 1) {
            int t = __shfl_up_sync(0xffffffffu, ws, o);
            if (lane >= o) ws += t;
        }
        if (lane < 8) wsum[lane] = ws;
    }
    __syncthreads();
    int run = sc - s + (w ? wsum[w - 1] : 0);
#pragma unroll
    for (int j = 0; j < 4; j++) {
        run += v[j];
        if (base + j < NN) g_rowptr[base + j + 1] = run;
    }
    if (tid == 255) g_bsum[blockIdx.x] = run;
}

__global__ void k_finalize() {
    __shared__ int s_off;
    const int tid = threadIdx.x;
    const int seg = blockIdx.x >> 2;
    if (tid < 32) {
        int acc = 0;
        for (int j = tid; j < seg; j += 32) acc += g_bsum[j];
#pragma unroll
        for (int o = 16; o; o >>= 1) acc += __shfl_xor_sync(0xffffffffu, acc, o);
        if (tid == 0) s_off = acc;
    }
    __syncthreads();
    int i = blockIdx.x * 256 + tid;
    if (i >= NN) return;
    int deg = g_degi[i];
    g_degi[i] = 0;
    int r = g_rowptr[i + 1] + s_off;
    g_rowptr[i + 1] = r;
    g_cursor[i] = r - deg;
    g_dinv[i] = rsqrtf((float)deg);
    if (i == 0) g_rowptr[0] = 0;
}

__global__ void k_fill(const int* __restrict__ ei) {
    int e = blockIdx.x * blockDim.x + threadIdx.x;
    if (e >= ETH) return;
    int s0 = (e < NE) ? ei[e]      : (e - NE);
    int d0 = (e < NE) ? ei[NE + e] : (e - NE);
    int p0 = atomicAdd(&g_cursor[d0], 1);
    g_csrc[p0] = s0;
    int e2 = e + ETH;
    if (e2 < ET) {
        int s1 = (e2 < NE) ? ei[e2]      : (e2 - NE);
        int d1 = (e2 < NE) ? ei[NE + e2] : (e2 - NE);
        int p1 = atomicAdd(&g_cursor[d1], 1);
        g_csrc[p1] = s1;
    }
}

// ---------------- fp32 -> fp16 conversion ----------
__global__ void k_h2h(const float* __restrict__ x) {
    int i = blockIdx.x * blockDim.x + threadIdx.x;
    if (i >= NN * D / 8) return;
    float4 a = ((const float4*)x)[2 * i], b = ((const float4*)x)[2 * i + 1];
    uint4 v;
    *(__half2*)&v.x = __floats2half2_rn(a.x, a.y);
    *(__half2*)&v.y = __floats2half2_rn(a.z, a.w);
    *(__half2*)&v.z = __floats2half2_rn(b.x, b.y);
    *(__half2*)&v.w = __floats2half2_rn(b.z, b.w);
    ((uint4*)g_hh)[i] = v;
}

// ---------------- fp16 tensor-core GEMM (unchanged from R10) ----------
__device__ __forceinline__ void mma_f16(float* c, const uint32_t* a, const uint32_t* b) {
    asm volatile(
        "mma.sync.aligned.m16n8k16.row.col.f32.f16.f16.f32 "
        "{%0,%1,%2,%3}, {%4,%5,%6,%7}, {%8,%9}, {%0,%1,%2,%3};"
        : "+f"(c[0]), "+f"(c[1]), "+f"(c[2]), "+f"(c[3])
        : "r"(a[0]), "r"(a[1]), "r"(a[2]), "r"(a[3]), "r"(b[0]), "r"(b[1]));
}

__device__ __forceinline__ void gemm_gload(const __half* __restrict__ A,
                                           const float* __restrict__ W,
                                           int M, int m0, int tid, int k0,
                                           uint4* ra, float4* rb) {
    int row = tid >> 1;
    int k8 = (tid & 1) * 8;
    uint4 v = make_uint4(0u, 0u, 0u, 0u);
    if (m0 + row < M) v = *(const uint4*)&A[(size_t)(m0 + row) * D + k0 + k8];
    *ra = v;
#pragma unroll
    for (int i = 0; i < 2; i++) {
        int f = tid * 2 + i;
        int kl = f >> 5;
        int n4 = (f & 31) * 4;
        rb[i] = *(const float4*)&W[(size_t)(k0 + kl) * D + n4];
    }
}

__device__ __forceinline__ void gemm_sstore(uint32_t (&As)[8][32][4],
                                            uint32_t (&Bs)[16][32][2],
                                            const uint4& ra, const float4* rb, int tid) {
    int row = tid >> 1;
    int k8 = (tid & 1) * 8;
    int mt = row >> 4, mr = row & 15;
    const uint32_t av[4] = {ra.x, ra.y, ra.z, ra.w};
#pragma unroll
    for (int jj = 0; jj < 4; jj++) {
        int kk = k8 + jj * 2;
        As[mt][(mr & 7) * 4 + ((kk & 7) >> 1)][(mr >> 3) | ((kk >> 3) << 1)] = av[jj];
    }
#pragma unroll
    for (int i = 0; i < 2; i++) {
        int f = tid * 2 + i;
        int kk = f >> 5;
        int n4 = (f & 31) * 4;
        float ww[4] = {rb[i].x, rb[i].y, rb[i].z, rb[i].w};
#pragma unroll
        for (int j = 0; j < 4; j++) {
            int n = n4 + j;
            __half* hp = (__half*)&Bs[n >> 3][(n & 7) * 4 + ((kk & 7) >> 1)][kk >> 3];
            hp[kk & 1] = __float2half_rn(ww[j]);
        }
    }
}

__global__ void __launch_bounds__(256) k_gemm(const __half* __restrict__ A,
                                              const float* __restrict__ W,
                                              __half* __restrict__ C, int M,
                                              const float* __restrict__ rowscale,
                                              const float* __restrict__ ws,
                                              const float* __restrict__ wd) {
    __shared__ uint32_t As[2][8][32][4];
    __shared__ uint32_t Bs[2][16][32][2];
    const int tid = threadIdx.x;
    const int lane = tid & 31;
    const int warp = tid >> 5;
    const int wm = warp >> 1;
    const int wn = warp & 1;
    const int m0 = blockIdx.x * 128;

    float acc[2][8][4];
#pragma unroll
    for (int i = 0; i < 2; i++)
#pragma unroll
        for (int j = 0; j < 8; j++)
#pragma unroll
            for (int q = 0; q < 4; q++) acc[i][j][q] = 0.f;

    uint4 ra; float4 rb[2];
    gemm_gload(A, W, M, m0, tid, 0, &ra, rb);
    gemm_sstore(As[0], Bs[0], ra, rb, tid);
    __syncthreads();
    int buf = 0;

    for (int k0 = 0; k0 < 128; k0 += 16) {
        const bool more = (k0 + 16 < 128);
        if (more) gemm_gload(A, W, M, m0, tid, k0 + 16, &ra, rb);
        uint32_t afr[2][4];
#pragma unroll
        for (int mf = 0; mf < 2; mf++) {
            uint4 t = *(const uint4*)&As[buf][wm * 2 + mf][lane][0];
            afr[mf][0] = t.x; afr[mf][1] = t.y; afr[mf][2] = t.z; afr[mf][3] = t.w;
        }
        uint32_t bfr[8][2];
#pragma unroll
        for (int nf = 0; nf < 8; nf++) {
            uint2 t = *(const uint2*)&Bs[buf][wn * 8 + nf][lane][0];
            bfr[nf][0] = t.x; bfr[nf][1] = t.y;
        }
#pragma unroll
        for (int mf = 0; mf < 2; mf++)
#pragma unroll
            for (int nf = 0; nf < 8; nf++)
                mma_f16(acc[mf][nf], afr[mf], bfr[nf]);
        if (more) {
            gemm_sstore(As[buf ^ 1], Bs[buf ^ 1], ra, rb, tid);
            __syncthreads();
            buf ^= 1;
        }
    }

    const int g = lane >> 2, q = lane & 3;
#pragma unroll
    for (int mf = 0; mf < 2; mf++) {
        int row0 = m0 + wm * 32 + mf * 16 + g;
        int row1 = row0 + 8;
        float s0 = 1.f, s1 = 1.f;
        if (rowscale) {
            if (row0 < M) s0 = rowscale[row0];
            if (row1 < M) s1 = rowscale[row1];
        }
#pragma unroll
        for (int nf = 0; nf < 8; nf++) {
            int colh = wn * 32 + nf * 4 + q;
            if (row0 < M)
                ((__half2*)C)[(size_t)row0 * 64 + colh] =
                    __floats2half2_rn(acc[mf][nf][0] * s0, acc[mf][nf][1] * s0);
            if (row1 < M)
                ((__half2*)C)[(size_t)row1 * 64 + colh] =
                    __floats2half2_rn(acc[mf][nf][2] * s1, acc[mf][nf][3] * s1);
        }
    }

    if (ws) {
        const int h0 = 2 * wn, h1 = 2 * wn + 1;
#pragma unroll
        for (int mf = 0; mf < 2; mf++) {
            int row0 = m0 + wm * 32 + mf * 16 + g;
            int row1 = row0 + 8;
            float sA0 = 0.f, dA0 = 0.f, sB0 = 0.f, dB0 = 0.f;
            float sA1 = 0.f, dA1 = 0.f, sB1 = 0.f, dB1 = 0.f;
#pragma unroll
            for (int nf = 0; nf < 8; nf++) {
                int col = (nf & 3) * 8 + q * 2;
                int h = (nf < 4) ? h0 : h1;
                float w0 = ws[h * HD + col], w1 = ws[h * HD + col + 1];
                float e0 = wd[h * HD + col], e1 = wd[h * HD + col + 1];
                float p0 = acc[mf][nf][0] * w0 + acc[mf][nf][1] * w1;
                float p1 = acc[mf][nf][0] * e0 + acc[mf][nf][1] * e1;
                float p2 = acc[mf][nf][2] * w0 + acc[mf][nf][3] * w1;
                float p3 = acc[mf][nf][2] * e0 + acc[mf][nf][3] * e1;
                if (nf < 4) { sA0 += p0; dA0 += p1; sA1 += p2; dA1 += p3; }
                else        { sB0 += p0; dB0 += p1; sB1 += p2; dB1 += p3; }
            }
#pragma unroll
            for (int o = 1; o <= 2; o <<= 1) {
                sA0 += __shfl_xor_sync(0xffffffffu, sA0, o);
                dA0 += __shfl_xor_sync(0xffffffffu, dA0, o);
                sB0 += __shfl_xor_sync(0xffffffffu, sB0, o);
                dB0 += __shfl_xor_sync(0xffffffffu, dB0, o);
                sA1 += __shfl_xor_sync(0xffffffffu, sA1, o);
                dA1 += __shfl_xor_sync(0xffffffffu, dA1, o);
                sB1 += __shfl_xor_sync(0xffffffffu, sB1, o);
                dB1 += __shfl_xor_sync(0xffffffffu, dB1, o);
            }
            if (q == 0) {
                if (row0 < M) {
                    g_asrc[row0 * H + h0] = sA0; g_adst[row0 * H + h0] = dA0;
                    g_asrc[row0 * H + h1] = sB0; g_adst[row0 * H + h1] = dB0;
                }
                if (row1 < M) {
                    g_asrc[row1 * H + h0] = sA1; g_adst[row1 * H + h0] = dA1;
                    g_asrc[row1 * H + h1] = sB1; g_adst[row1 * H + h1] = dB1;
                }
            }
        }
    }
}

// ---------------- GCN aggregation (warp per dst, R10 unrolled fp16 gather) -----
__global__ void k_gcn_agg(const float* __restrict__ b) {
    __shared__ int s_src[8][32];
    int gt = blockIdx.x * blockDim.x + threadIdx.x;
    int n = gt >> 5, lane = gt & 31, w = threadIdx.x >> 5;
    if (n >= NN) return;
    const int start = g_rowptr[n], end = g_rowptr[n + 1];
    float4 acc = make_float4(0.f, 0.f, 0.f, 0.f);
    for (int j0 = start; j0 < end; j0 += 32) {
        int jj = j0 + lane;
        if (jj < end) s_src[w][lane] = g_csrc[jj];
        __syncwarp();
        int cnt = min(32, end - j0);
        int t = 0;
        for (; t + 4 <= cnt; t += 4) {
            int s0 = s_src[w][t], s1 = s_src[w][t + 1];
            int s2 = s_src[w][t + 2], s3 = s_src[w][t + 3];
            uint2 u0 = ((const uint2*)g_xwh)[s0 * 32 + lane];
            uint2 u1 = ((const uint2*)g_xwh)[s1 * 32 + lane];
            uint2 u2 = ((const uint2*)g_xwh)[s2 * 32 + lane];
            uint2 u3 = ((const uint2*)g_xwh)[s3 * 32 + lane];
            float2 a0 = __half22float2(*(__half2*)&u0.x), b0 = __half22float2(*(__half2*)&u0.y);
            float2 a1 = __half22float2(*(__half2*)&u1.x), b1 = __half22float2(*(__half2*)&u1.y);
            float2 a2 = __half22float2(*(__half2*)&u2.x), b2 = __half22float2(*(__half2*)&u2.y);
            float2 a3 = __half22float2(*(__half2*)&u3.x), b3 = __half22float2(*(__half2*)&u3.y);
            acc.x += (a0.x + a1.x) + (a2.x + a3.x);
            acc.y += (a0.y + a1.y) + (a2.y + a3.y);
            acc.z += (b0.x + b1.x) + (b2.x + b3.x);
            acc.w += (b0.y + b1.y) + (b2.y + b3.y);
        }
        for (; t < cnt; t++) {
            int s = s_src[w][t];
            uint2 u = ((const uint2*)g_xwh)[s * 32 + lane];
            float2 f0 = __half22float2(*(__half2*)&u.x);
            float2 f1 = __half22float2(*(__half2*)&u.y);
            acc.x += f0.x; acc.y += f0.y; acc.z += f1.x; acc.w += f1.y;
        }
        __syncwarp();
    }
    const float din = g_dinv[n];
    float4 bb = ((const float4*)b)[lane];
    float4 o;
    o.x = fmaf(acc.x, din, bb.x);
    o.y = fmaf(acc.y, din, bb.y);
    o.z = fmaf(acc.z, din, bb.z);
    o.w = fmaf(acc.w, din, bb.w);
    ((float4*)g_hgcn)[n * 32 + lane] = o;
    uint2 hv;
    *(__half2*)&hv.x = __floats2half2_rn(o.x, o.y);
    *(__half2*)&hv.y = __floats2half2_rn(o.z, o.w);
    ((uint2*)g_hgcnh)[n * 32 + lane] = hv;
}

__device__ __forceinline__ float lrelu(float v) { return (v > 0.f) ? v : NEG * v; }

// ---------------- GAT + residual + LayerNorm + ReLU (warp per dst) ----------------
// Fast path for deg<=32 (common, mean deg ~17): compute unnormalized exp once,
// normalize in smem after the z-reduction, reuse in the gather.
__global__ void k_gat_ln(const float* __restrict__ gb, const float* __restrict__ lg,
                         const float* __restrict__ lb, float* __restrict__ outf,
                         __half* __restrict__ outh) {
    __shared__ int    s_src[8][32];
    __shared__ float4 s_al[8][32];
    int gt = blockIdx.x * blockDim.x + threadIdx.x;
    int n = gt >> 5, lane = gt & 31, w = threadIdx.x >> 5;
    if (n >= NN) return;
    const int start = g_rowptr[n], end = g_rowptr[n + 1];
    const int deg = end - start;
    const float4 ad = ((const float4*)g_adst)[n];
    const int hsel = lane >> 3;
    float4 acc = ((const float4*)gb)[lane];

    if (deg <= 32) {
        // single-chunk fast path
        float4 e = make_float4(0.f, 0.f, 0.f, 0.f);
        if (lane < deg) {
            int src = g_csrc[start + lane];
            float4 as = ((const float4*)g_asrc)[src];
            e.x = __expf(lrelu(as.x + ad.x));
            e.y = __expf(lrelu(as.y + ad.y));
            e.z = __expf(lrelu(as.z + ad.z));
            e.w = __expf(lrelu(as.w + ad.w));
            s_src[w][lane] = src;
        }
        float z0 = e.x, z1 = e.y, z2 = e.z, z3 = e.w;
#pragma unroll
        for (int o = 16; o; o >>= 1) {
            z0 += __shfl_xor_sync(0xffffffffu, z0, o);
            z1 += __shfl_xor_sync(0xffffffffu, z1, o);
            z2 += __shfl_xor_sync(0xffffffffu, z2, o);
            z3 += __shfl_xor_sync(0xffffffffu, z3, o);
        }
        if (lane < deg) {
            e.x /= z0; e.y /= z1; e.z /= z2; e.w /= z3;
            s_al[w][lane] = e;
        }
        __syncwarp();
        int t = 0;
        for (; t + 4 <= deg; t += 4) {
            int s0 = s_src[w][t], s1 = s_src[w][t + 1];
            int s2 = s_src[w][t + 2], s3 = s_src[w][t + 3];
            float a0 = ((const float*)&s_al[w][t])[hsel];
            float a1 = ((const float*)&s_al[w][t + 1])[hsel];
            float a2 = ((const float*)&s_al[w][t + 2])[hsel];
            float a3 = ((const float*)&s_al[w][t + 3])[hsel];
            uint2 u0 = ((const uint2*)g_xw2h)[s0 * 32 + lane];
            uint2 u1 = ((const uint2*)g_xw2h)[s1 * 32 + lane];
            uint2 u2 = ((const uint2*)g_xw2h)[s2 * 32 + lane];
            uint2 u3 = ((const uint2*)g_xw2h)[s3 * 32 + lane];
            float2 p0 = __half22float2(*(__half2*)&u0.x), q0 = __half22float2(*(__half2*)&u0.y);
            float2 p1 = __half22float2(*(__half2*)&u1.x), q1 = __half22float2(*(__half2*)&u1.y);
            float2 p2 = __half22float2(*(__half2*)&u2.x), q2 = __half22float2(*(__half2*)&u2.y);
            float2 p3 = __half22float2(*(__half2*)&u3.x), q3 = __half22float2(*(__half2*)&u3.y);
            acc.x = fmaf(p0.x, a0, fmaf(p1.x, a1, fmaf(p2.x, a2, fmaf(p3.x, a3, acc.x))));
            acc.y = fmaf(p0.y, a0, fmaf(p1.y, a1, fmaf(p2.y, a2, fmaf(p3.y, a3, acc.y))));
            acc.z = fmaf(q0.x, a0, fmaf(q1.x, a1, fmaf(q2.x, a2, fmaf(q3.x, a3, acc.z))));
            acc.w = fmaf(q0.y, a0, fmaf(q1.y, a1, fmaf(q2.y, a2, fmaf(q3.y, a3, acc.w))));
        }
        for (; t < deg; t++) {
            int src = s_src[w][t];
            float a = ((const float*)&s_al[w][t])[hsel];
            uint2 u = ((const uint2*)g_xw2h)[src * 32 + lane];
            float2 f0 = __half22float2(*(__half2*)&u.x);
            float2 f1 = __half22float2(*(__half2*)&u.y);
            acc.x = fmaf(f0.x, a, acc.x);
            acc.y = fmaf(f0.y, a, acc.y);
            acc.z = fmaf(f1.x, a, acc.z);
            acc.w = fmaf(f1.y, a, acc.w);
        }
        __syncwarp();
    } else {
        // general path (R10)
        float z0 = 0.f, z1 = 0.f, z2 = 0.f, z3 = 0.f;
        for (int j = start + lane; j < end; j += 32) {
            int src = g_csrc[j];
            float4 as = ((const float4*)g_asrc)[src];
            z0 += __expf(lrelu(as.x + ad.x));
            z1 += __expf(lrelu(as.y + ad.y));
            z2 += __expf(lrelu(as.z + ad.z));
            z3 += __expf(lrelu(as.w + ad.w));
        }
#pragma unroll
        for (int o = 16; o; o >>= 1) {
            z0 += __shfl_xor_sync(0xffffffffu, z0, o);
            z1 += __shfl_xor_sync(0xffffffffu, z1, o);
            z2 += __shfl_xor_sync(0xffffffffu, z2, o);
            z3 += __shfl_xor_sync(0xffffffffu, z3, o);
        }
        const float r0 = 1.f / z0, r1 = 1.f / z1, r2 = 1.f / z2, r3 = 1.f / z3;
        for (int j0 = start; j0 < end; j0 += 32) {
            int jj = j0 + lane;
            if (jj < end) {
                int src = g_csrc[jj];
                float4 as = ((const float4*)g_asrc)[src];
                float4 al;
                al.x = __expf(lrelu(as.x + ad.x)) * r0;
                al.y = __expf(lrelu(as.y + ad.y)) * r1;
                al.z = __expf(lrelu(as.z + ad.z)) * r2;
                al.w = __expf(lrelu(as.w + ad.w)) * r3;
                s_src[w][lane] = src;
                s_al[w][lane] = al;
            }
            __syncwarp();
            int cnt = min(32, end - j0);
            int t = 0;
            for (; t + 4 <= cnt; t += 4) {
                int s0 = s_src[w][t], s1 = s_src[w][t + 1];
                int s2 = s_src[w][t + 2], s3 = s_src[w][t + 3];
                float a0 = ((const float*)&s_al[w][t])[hsel];
                float a1 = ((const float*)&s_al[w][t + 1])[hsel];
                float a2 = ((const float*)&s_al[w][t + 2])[hsel];
                float a3 = ((const float*)&s_al[w][t + 3])[hsel];
                uint2 u0 = ((const uint2*)g_xw2h)[s0 * 32 + lane];
                uint2 u1 = ((const uint2*)g_xw2h)[s1 * 32 + lane];
                uint2 u2 = ((const uint2*)g_xw2h)[s2 * 32 + lane];
                uint2 u3 = ((const uint2*)g_xw2h)[s3 * 32 + lane];
                float2 p0 = __half22float2(*(__half2*)&u0.x), q0 = __half22float2(*(__half2*)&u0.y);
                float2 p1 = __half22float2(*(__half2*)&u1.x), q1 = __half22float2(*(__half2*)&u1.y);
                float2 p2 = __half22float2(*(__half2*)&u2.x), q2 = __half22float2(*(__half2*)&u2.y);
                float2 p3 = __half22float2(*(__half2*)&u3.x), q3 = __half22float2(*(__half2*)&u3.y);
                acc.x = fmaf(p0.x, a0, fmaf(p1.x, a1, fmaf(p2.x, a2, fmaf(p3.x, a3, acc.x))));
                acc.y = fmaf(p0.y, a0, fmaf(p1.y, a1, fmaf(p2.y, a2, fmaf(p3.y, a3, acc.y))));
                acc.z = fmaf(q0.x, a0, fmaf(q1.x, a1, fmaf(q2.x, a2, fmaf(q3.x, a3, acc.z))));
                acc.w = fmaf(q0.y, a0, fmaf(q1.y, a1, fmaf(q2.y, a2, fmaf(q3.y, a3, acc.w))));
            }
            for (; t < cnt; t++) {
                int src = s_src[w][t];
                float a = ((const float*)&s_al[w][t])[hsel];
                uint2 u = ((const uint2*)g_xw2h)[src * 32 + lane];
                float2 f0 = __half22float2(*(__half2*)&u.x);
                float2 f1 = __half22float2(*(__half2*)&u.y);
                acc.x = fmaf(f0.x, a, acc.x);
                acc.y = fmaf(f0.y, a, acc.y);
                acc.z = fmaf(f1.x, a, acc.z);
                acc.w = fmaf(f1.y, a, acc.w);
            }
            __syncwarp();
        }
    }

    // residual + LayerNorm + ReLU
    float4 c = ((const float4*)g_hgcn)[n * 32 + lane];
    acc.x += c.x; acc.y += c.y; acc.z += c.z; acc.w += c.w;
    float s = acc.x + acc.y + acc.z + acc.w;
#pragma unroll
    for (int o = 16; o; o >>= 1) s += __shfl_xor_sync(0xffffffffu, s, o);
    float mu = s * (1.0f / D);
    float dx = acc.x - mu, dy = acc.y - mu, dz = acc.z - mu, dw = acc.w - mu;
    float q = dx * dx + dy * dy + dz * dz + dw * dw;
#pragma unroll
    for (int o = 16; o; o >>= 1) q += __shfl_xor_sync(0xffffffffu, q, o);
    float rs = rsqrtf(q * (1.0f / D) + 1e-5f);
    float4 gg = ((const float4*)lg)[lane];
    float4 bb = ((const float4*)lb)[lane];
    float4 y;
    y.x = fmaxf(dx * rs * gg.x + bb.x, 0.f);
    y.y = fmaxf(dy * rs * gg.y + bb.y, 0.f);
    y.z = fmaxf(dz * rs * gg.z + bb.z, 0.f);
    y.w = fmaxf(dw * rs * gg.w + bb.w, 0.f);
    if (outf) {
        ((float4*)outf)[n * 32 + lane] = y;
    } else {
        uint2 hv;
        *(__half2*)&hv.x = __floats2half2_rn(y.x, y.y);
        *(__half2*)&hv.y = __floats2half2_rn(y.z, y.w);
        ((uint2*)outh)[n * 32 + lane] = hv;
    }
}

// ---------------- launch ----------------
extern "C" void kernel_launch(void* const* d_in, const int* in_sizes, int n_in,
                              void* d_out, int out_size) {
    const float* x      = (const float*)d_in[0];
    const int*   ei     = (const int*)  d_in[1];
    const float* gcn_w  = (const float*)d_in[2];
    const float* gcn_b  = (const float*)d_in[3];
    const float* gat_w  = (const float*)d_in[4];
    const float* att_s  = (const float*)d_in[5];
    const float* att_d  = (const float*)d_in[6];
    const float* gat_b  = (const float*)d_in[7];
    const float* ln_g   = (const float*)d_in[8];
    const float* ln_b   = (const float*)d_in[9];
    float* out = (float*)d_out;

    float  *p_dinv;
    __half *p_hh, *p_hgcnh, *p_xwh, *p_xw2h;
    cudaGetSymbolAddress((void**)&p_dinv,   g_dinv);
    cudaGetSymbolAddress((void**)&p_hh,     g_hh);
    cudaGetSymbolAddress((void**)&p_hgcnh,  g_hgcnh);
    cudaGetSymbolAddress((void**)&p_xwh,    g_xwh);
    cudaGetSymbolAddress((void**)&p_xw2h,   g_xw2h);

    const int T = 256;
    // CSR build (per replay; graph-capturable, no allocation).
    k_deg<<<cdiv(ETH, T), T>>>(ei);
    k_blockscan<<<NB, 256>>>();
    k_finalize<<<cdiv(NN, T), T>>>();
    k_fill<<<cdiv(ETH, T), T>>>(ei);
    // x -> fp16
    k_h2h<<<cdiv(NN * D / 8, T), T>>>(x);

    for (int l = 0; l < 3; l++) {
        // GCN (output pre-scaled by dinv[row])
        k_gemm<<<cdiv(NN, 128), T>>>(p_hh, gcn_w + l * D * D, p_xwh, NN, p_dinv,
                                     nullptr, nullptr);
        k_gcn_agg<<<cdiv(NN * 32, T), T>>>(gcn_b + l * D);
        // GAT (fused attention coefficients in epilogue)
        k_gemm<<<cdiv(NN, 128), T>>>(p_hgcnh, gat_w + l * D * D, p_xw2h, NN, nullptr,
                                     att_s + l * H * HD, att_d + l * H * HD);
        // GAT aggregation + residual + LN + ReLU fused
        if (l == 2)
            k_gat_ln<<<cdiv(NN * 32, T), T>>>(gat_b + l * D, ln_g + l * D, ln_b + l * D,
                                              out, nullptr);
        else
            k_gat_ln<<<cdiv(NN * 32, T), T>>>(gat_b + l * D, ln_g + l * D, ln_b + l * D,
                                              nullptr, p_hh);
    }
}

// round 14
// speedup vs baseline: 1.2320x; 1.0119x over previous
#include <cuda_runtime.h>
#include <cuda_fp16.h>
#include <math.h>
#include <stdint.h>

#define NN 50000
#define NE 800000
#define ET (NE + NN)          // edges + self loops
#define D 128
#define H 4
#define HD 32
#define NEG 0.2f
#define NB 49                 // cdiv(NN, 1024) scan blocks
#define ETH ((ET + 1) / 2)    // half split for ILP-2 edge kernels

// ---------------- scratch (static device globals; no allocation) ----------------
__device__ __half g_hh[NN * D];     // layer input features (fp16)
__device__ __half g_xwh[NN * D];    // GCN x@W * dinv[row]  (fp16, gathered)
__device__ __half g_hgcnh[NN * D];  // GCN layer output (fp16: GEMM input + residual)
__device__ __half g_xw2h[NN * D];   // GAT x@W  (fp16, gathered)
__device__ float  g_dinv[NN];
__device__ float  g_asrc[NN * H];
__device__ float  g_adst[NN * H];
__device__ int    g_degi[NN];       // zero at entry of every launch (finalize restores)
__device__ int    g_rowptr[NN + 1];
__device__ int    g_cursor[NN];
__device__ int    g_csrc[ET];
__device__ int    g_bsum[NB];

static inline int cdiv(int a, int b) { return (a + b - 1) / b; }

// ---------------- CSR build (ILP-2) --------
__global__ void k_deg(const int* __restrict__ ei) {
    int e = blockIdx.x * blockDim.x + threadIdx.x;
    if (e >= ETH) return;
    int d0 = (e < NE) ? ei[NE + e] : (e - NE);
    atomicAdd(&g_degi[d0], 1);
    int e2 = e + ETH;
    if (e2 < ET) {
        int d1 = (e2 < NE) ? ei[NE + e2] : (e2 - NE);
        atomicAdd(&g_degi[d1], 1);
    }
}

__global__ void k_blockscan() {
    __shared__ int wsum[8];
    const int tid = threadIdx.x;
    const int lane = tid & 31, w = tid >> 5;
    const int base = blockIdx.x * 1024 + tid * 4;
    int v[4];
    int s = 0;
#pragma unroll
    for (int j = 0; j < 4; j++) {
        v[j] = (base + j < NN) ? g_degi[base + j] : 0;
        s += v[j];
    }
    int sc = s;
#pragma unroll
    for (int o = 1; o < 32; o <<= 1) {
        int t = __shfl_up_sync(0xffffffffu, sc, o);
        if (lane >= o) sc += t;
    }
    if (lane == 31) wsum[w] = sc;
    __syncthreads();
    if (w == 0) {
        int ws = (lane < 8) ? wsum[lane] : 0;
#pragma unroll
        for (int o = 1; o < 8; o <<= 1) {
            int t = __shfl_up_sync(0xffffffffu, ws, o);
            if (lane >= o) ws += t;
        }
        if (lane < 8) wsum[lane] = ws;
    }
    __syncthreads();
    int run = sc - s + (w ? wsum[w - 1] : 0);
#pragma unroll
    for (int j = 0; j < 4; j++) {
        run += v[j];
        if (base + j < NN) g_rowptr[base + j + 1] = run;
    }
    if (tid == 255) g_bsum[blockIdx.x] = run;
}

__global__ void k_finalize() {
    __shared__ int s_off;
    const int tid = threadIdx.x;
    const int seg = blockIdx.x >> 2;
    if (tid < 32) {
        int acc = 0;
        for (int j = tid; j < seg; j += 32) acc += g_bsum[j];
#pragma unroll
        for (int o = 16; o; o >>= 1) acc += __shfl_xor_sync(0xffffffffu, acc, o);
        if (tid == 0) s_off = acc;
    }
    __syncthreads();
    int i = blockIdx.x * 256 + tid;
    if (i >= NN) return;
    int deg = g_degi[i];
    g_degi[i] = 0;
    int r = g_rowptr[i + 1] + s_off;
    g_rowptr[i + 1] = r;
    g_cursor[i] = r - deg;
    g_dinv[i] = rsqrtf((float)deg);
    if (i == 0) g_rowptr[0] = 0;
}

__global__ void k_fill(const int* __restrict__ ei) {
    int e = blockIdx.x * blockDim.x + threadIdx.x;
    if (e >= ETH) return;
    int s0 = (e < NE) ? ei[e]      : (e - NE);
    int d0 = (e < NE) ? ei[NE + e] : (e - NE);
    int p0 = atomicAdd(&g_cursor[d0], 1);
    g_csrc[p0] = s0;
    int e2 = e + ETH;
    if (e2 < ET) {
        int s1 = (e2 < NE) ? ei[e2]      : (e2 - NE);
        int d1 = (e2 < NE) ? ei[NE + e2] : (e2 - NE);
        int p1 = atomicAdd(&g_cursor[d1], 1);
        g_csrc[p1] = s1;
    }
}

// ---------------- fp32 -> fp16 conversion ----------
__global__ void k_h2h(const float* __restrict__ x) {
    int i = blockIdx.x * blockDim.x + threadIdx.x;
    if (i >= NN * D / 8) return;
    float4 a = ((const float4*)x)[2 * i], b = ((const float4*)x)[2 * i + 1];
    uint4 v;
    *(__half2*)&v.x = __floats2half2_rn(a.x, a.y);
    *(__half2*)&v.y = __floats2half2_rn(a.z, a.w);
    *(__half2*)&v.z = __floats2half2_rn(b.x, b.y);
    *(__half2*)&v.w = __floats2half2_rn(b.z, b.w);
    ((uint4*)g_hh)[i] = v;
}

// ---------------- fp16 tensor-core GEMM (unchanged from R10) ----------
__device__ __forceinline__ void mma_f16(float* c, const uint32_t* a, const uint32_t* b) {
    asm volatile(
        "mma.sync.aligned.m16n8k16.row.col.f32.f16.f16.f32 "
        "{%0,%1,%2,%3}, {%4,%5,%6,%7}, {%8,%9}, {%0,%1,%2,%3};"
        : "+f"(c[0]), "+f"(c[1]), "+f"(c[2]), "+f"(c[3])
        : "r"(a[0]), "r"(a[1]), "r"(a[2]), "r"(a[3]), "r"(b[0]), "r"(b[1]));
}

__device__ __forceinline__ void gemm_gload(const __half* __restrict__ A,
                                           const float* __restrict__ W,
                                           int M, int m0, int tid, int k0,
                                           uint4* ra, float4* rb) {
    int row = tid >> 1;
    int k8 = (tid & 1) * 8;
    uint4 v = make_uint4(0u, 0u, 0u, 0u);
    if (m0 + row < M) v = *(const uint4*)&A[(size_t)(m0 + row) * D + k0 + k8];
    *ra = v;
#pragma unroll
    for (int i = 0; i < 2; i++) {
        int f = tid * 2 + i;
        int kl = f >> 5;
        int n4 = (f & 31) * 4;
        rb[i] = *(const float4*)&W[(size_t)(k0 + kl) * D + n4];
    }
}

__device__ __forceinline__ void gemm_sstore(uint32_t (&As)[8][32][4],
                                            uint32_t (&Bs)[16][32][2],
                                            const uint4& ra, const float4* rb, int tid) {
    int row = tid >> 1;
    int k8 = (tid & 1) * 8;
    int mt = row >> 4, mr = row & 15;
    const uint32_t av[4] = {ra.x, ra.y, ra.z, ra.w};
#pragma unroll
    for (int jj = 0; jj < 4; jj++) {
        int kk = k8 + jj * 2;
        As[mt][(mr & 7) * 4 + ((kk & 7) >> 1)][(mr >> 3) | ((kk >> 3) << 1)] = av[jj];
    }
#pragma unroll
    for (int i = 0; i < 2; i++) {
        int f = tid * 2 + i;
        int kk = f >> 5;
        int n4 = (f & 31) * 4;
        float ww[4] = {rb[i].x, rb[i].y, rb[i].z, rb[i].w};
#pragma unroll
        for (int j = 0; j < 4; j++) {
            int n = n4 + j;
            __half* hp = (__half*)&Bs[n >> 3][(n & 7) * 4 + ((kk & 7) >> 1)][kk >> 3];
            hp[kk & 1] = __float2half_rn(ww[j]);
        }
    }
}

__global__ void __launch_bounds__(256) k_gemm(const __half* __restrict__ A,
                                              const float* __restrict__ W,
                                              __half* __restrict__ C, int M,
                                              const float* __restrict__ rowscale,
                                              const float* __restrict__ ws,
                                              const float* __restrict__ wd) {
    __shared__ uint32_t As[2][8][32][4];
    __shared__ uint32_t Bs[2][16][32][2];
    const int tid = threadIdx.x;
    const int lane = tid & 31;
    const int warp = tid >> 5;
    const int wm = warp >> 1;
    const int wn = warp & 1;
    const int m0 = blockIdx.x * 128;

    float acc[2][8][4];
#pragma unroll
    for (int i = 0; i < 2; i++)
#pragma unroll
        for (int j = 0; j < 8; j++)
#pragma unroll
            for (int q = 0; q < 4; q++) acc[i][j][q] = 0.f;

    uint4 ra; float4 rb[2];
    gemm_gload(A, W, M, m0, tid, 0, &ra, rb);
    gemm_sstore(As[0], Bs[0], ra, rb, tid);
    __syncthreads();
    int buf = 0;

    for (int k0 = 0; k0 < 128; k0 += 16) {
        const bool more = (k0 + 16 < 128);
        if (more) gemm_gload(A, W, M, m0, tid, k0 + 16, &ra, rb);
        uint32_t afr[2][4];
#pragma unroll
        for (int mf = 0; mf < 2; mf++) {
            uint4 t = *(const uint4*)&As[buf][wm * 2 + mf][lane][0];
            afr[mf][0] = t.x; afr[mf][1] = t.y; afr[mf][2] = t.z; afr[mf][3] = t.w;
        }
        uint32_t bfr[8][2];
#pragma unroll
        for (int nf = 0; nf < 8; nf++) {
            uint2 t = *(const uint2*)&Bs[buf][wn * 8 + nf][lane][0];
            bfr[nf][0] = t.x; bfr[nf][1] = t.y;
        }
#pragma unroll
        for (int mf = 0; mf < 2; mf++)
#pragma unroll
            for (int nf = 0; nf < 8; nf++)
                mma_f16(acc[mf][nf], afr[mf], bfr[nf]);
        if (more) {
            gemm_sstore(As[buf ^ 1], Bs[buf ^ 1], ra, rb, tid);
            __syncthreads();
            buf ^= 1;
        }
    }

    const int g = lane >> 2, q = lane & 3;
#pragma unroll
    for (int mf = 0; mf < 2; mf++) {
        int row0 = m0 + wm * 32 + mf * 16 + g;
        int row1 = row0 + 8;
        float s0 = 1.f, s1 = 1.f;
        if (rowscale) {
            if (row0 < M) s0 = rowscale[row0];
            if (row1 < M) s1 = rowscale[row1];
        }
#pragma unroll
        for (int nf = 0; nf < 8; nf++) {
            int colh = wn * 32 + nf * 4 + q;
            if (row0 < M)
                ((__half2*)C)[(size_t)row0 * 64 + colh] =
                    __floats2half2_rn(acc[mf][nf][0] * s0, acc[mf][nf][1] * s0);
            if (row1 < M)
                ((__half2*)C)[(size_t)row1 * 64 + colh] =
                    __floats2half2_rn(acc[mf][nf][2] * s1, acc[mf][nf][3] * s1);
        }
    }

    if (ws) {
        const int h0 = 2 * wn, h1 = 2 * wn + 1;
#pragma unroll
        for (int mf = 0; mf < 2; mf++) {
            int row0 = m0 + wm * 32 + mf * 16 + g;
            int row1 = row0 + 8;
            float sA0 = 0.f, dA0 = 0.f, sB0 = 0.f, dB0 = 0.f;
            float sA1 = 0.f, dA1 = 0.f, sB1 = 0.f, dB1 = 0.f;
#pragma unroll
            for (int nf = 0; nf < 8; nf++) {
                int col = (nf & 3) * 8 + q * 2;
                int h = (nf < 4) ? h0 : h1;
                float w0 = ws[h * HD + col], w1 = ws[h * HD + col + 1];
                float e0 = wd[h * HD + col], e1 = wd[h * HD + col + 1];
                float p0 = acc[mf][nf][0] * w0 + acc[mf][nf][1] * w1;
                float p1 = acc[mf][nf][0] * e0 + acc[mf][nf][1] * e1;
                float p2 = acc[mf][nf][2] * w0 + acc[mf][nf][3] * w1;
                float p3 = acc[mf][nf][2] * e0 + acc[mf][nf][3] * e1;
                if (nf < 4) { sA0 += p0; dA0 += p1; sA1 += p2; dA1 += p3; }
                else        { sB0 += p0; dB0 += p1; sB1 += p2; dB1 += p3; }
            }
#pragma unroll
            for (int o = 1; o <= 2; o <<= 1) {
                sA0 += __shfl_xor_sync(0xffffffffu, sA0, o);
                dA0 += __shfl_xor_sync(0xffffffffu, dA0, o);
                sB0 += __shfl_xor_sync(0xffffffffu, sB0, o);
                dB0 += __shfl_xor_sync(0xffffffffu, dB0, o);
                sA1 += __shfl_xor_sync(0xffffffffu, sA1, o);
                dA1 += __shfl_xor_sync(0xffffffffu, dA1, o);
                sB1 += __shfl_xor_sync(0xffffffffu, sB1, o);
                dB1 += __shfl_xor_sync(0xffffffffu, dB1, o);
            }
            if (q == 0) {
                if (row0 < M) {
                    g_asrc[row0 * H + h0] = sA0; g_adst[row0 * H + h0] = dA0;
                    g_asrc[row0 * H + h1] = sB0; g_adst[row0 * H + h1] = dB0;
                }
                if (row1 < M) {
                    g_asrc[row1 * H + h0] = sA1; g_adst[row1 * H + h0] = dA1;
                    g_asrc[row1 * H + h1] = sB1; g_adst[row1 * H + h1] = dB1;
                }
            }
        }
    }
}

// ---------------- GCN aggregation (warp per dst, R10 unrolled fp16 gather) -----
// xwh pre-scaled by dinv[src]; out = (sum xwh[src]) * dinv[dst] + bias.
// Single fp16 output (GEMM input AND residual source).
__global__ void k_gcn_agg(const float* __restrict__ b) {
    __shared__ int s_src[8][32];
    int gt = blockIdx.x * blockDim.x + threadIdx.x;
    int n = gt >> 5, lane = gt & 31, w = threadIdx.x >> 5;
    if (n >= NN) return;
    const int start = g_rowptr[n], end = g_rowptr[n + 1];
    float4 acc = make_float4(0.f, 0.f, 0.f, 0.f);
    for (int j0 = start; j0 < end; j0 += 32) {
        int jj = j0 + lane;
        if (jj < end) s_src[w][lane] = g_csrc[jj];
        __syncwarp();
        int cnt = min(32, end - j0);
        int t = 0;
        for (; t + 4 <= cnt; t += 4) {
            int s0 = s_src[w][t], s1 = s_src[w][t + 1];
            int s2 = s_src[w][t + 2], s3 = s_src[w][t + 3];
            uint2 u0 = ((const uint2*)g_xwh)[s0 * 32 + lane];
            uint2 u1 = ((const uint2*)g_xwh)[s1 * 32 + lane];
            uint2 u2 = ((const uint2*)g_xwh)[s2 * 32 + lane];
            uint2 u3 = ((const uint2*)g_xwh)[s3 * 32 + lane];
            float2 a0 = __half22float2(*(__half2*)&u0.x), b0 = __half22float2(*(__half2*)&u0.y);
            float2 a1 = __half22float2(*(__half2*)&u1.x), b1 = __half22float2(*(__half2*)&u1.y);
            float2 a2 = __half22float2(*(__half2*)&u2.x), b2 = __half22float2(*(__half2*)&u2.y);
            float2 a3 = __half22float2(*(__half2*)&u3.x), b3 = __half22float2(*(__half2*)&u3.y);
            acc.x += (a0.x + a1.x) + (a2.x + a3.x);
            acc.y += (a0.y + a1.y) + (a2.y + a3.y);
            acc.z += (b0.x + b1.x) + (b2.x + b3.x);
            acc.w += (b0.y + b1.y) + (b2.y + b3.y);
        }
        for (; t < cnt; t++) {
            int s = s_src[w][t];
            uint2 u = ((const uint2*)g_xwh)[s * 32 + lane];
            float2 f0 = __half22float2(*(__half2*)&u.x);
            float2 f1 = __half22float2(*(__half2*)&u.y);
            acc.x += f0.x; acc.y += f0.y; acc.z += f1.x; acc.w += f1.y;
        }
        __syncwarp();
    }
    const float din = g_dinv[n];
    float4 bb = ((const float4*)b)[lane];
    uint2 hv;
    *(__half2*)&hv.x = __floats2half2_rn(fmaf(acc.x, din, bb.x), fmaf(acc.y, din, bb.y));
    *(__half2*)&hv.y = __floats2half2_rn(fmaf(acc.z, din, bb.z), fmaf(acc.w, din, bb.w));
    ((uint2*)g_hgcnh)[n * 32 + lane] = hv;
}

__device__ __forceinline__ float lrelu(float v) { return (v > 0.f) ? v : NEG * v; }

// ---------------- GAT + residual + LayerNorm + ReLU (warp per dst) ----------------
__global__ void k_gat_ln(const float* __restrict__ gb, const float* __restrict__ lg,
                         const float* __restrict__ lb, float* __restrict__ outf,
                         __half* __restrict__ outh) {
    __shared__ int    s_src[8][32];
    __shared__ float4 s_al[8][32];
    int gt = blockIdx.x * blockDim.x + threadIdx.x;
    int n = gt >> 5, lane = gt & 31, w = threadIdx.x >> 5;
    if (n >= NN) return;
    const int start = g_rowptr[n], end = g_rowptr[n + 1];
    const int deg = end - start;
    const float4 ad = ((const float4*)g_adst)[n];
    const int hsel = lane >> 3;
    float4 acc = ((const float4*)gb)[lane];

    if (deg <= 32) {
        // single-chunk fast path: exp computed once, normalized in smem
        float4 e = make_float4(0.f, 0.f, 0.f, 0.f);
        if (lane < deg) {
            int src = g_csrc[start + lane];
            float4 as = ((const float4*)g_asrc)[src];
            e.x = __expf(lrelu(as.x + ad.x));
            e.y = __expf(lrelu(as.y + ad.y));
            e.z = __expf(lrelu(as.z + ad.z));
            e.w = __expf(lrelu(as.w + ad.w));
            s_src[w][lane] = src;
        }
        float z0 = e.x, z1 = e.y, z2 = e.z, z3 = e.w;
#pragma unroll
        for (int o = 16; o; o >>= 1) {
            z0 += __shfl_xor_sync(0xffffffffu, z0, o);
            z1 += __shfl_xor_sync(0xffffffffu, z1, o);
            z2 += __shfl_xor_sync(0xffffffffu, z2, o);
            z3 += __shfl_xor_sync(0xffffffffu, z3, o);
        }
        if (lane < deg) {
            e.x *= __frcp_rn(z0); e.y *= __frcp_rn(z1);
            e.z *= __frcp_rn(z2); e.w *= __frcp_rn(z3);
            s_al[w][lane] = e;
        }
        __syncwarp();
        int t = 0;
        for (; t + 4 <= deg; t += 4) {
            int s0 = s_src[w][t], s1 = s_src[w][t + 1];
            int s2 = s_src[w][t + 2], s3 = s_src[w][t + 3];
            float a0 = ((const float*)&s_al[w][t])[hsel];
            float a1 = ((const float*)&s_al[w][t + 1])[hsel];
            float a2 = ((const float*)&s_al[w][t + 2])[hsel];
            float a3 = ((const float*)&s_al[w][t + 3])[hsel];
            uint2 u0 = ((const uint2*)g_xw2h)[s0 * 32 + lane];
            uint2 u1 = ((const uint2*)g_xw2h)[s1 * 32 + lane];
            uint2 u2 = ((const uint2*)g_xw2h)[s2 * 32 + lane];
            uint2 u3 = ((const uint2*)g_xw2h)[s3 * 32 + lane];
            float2 p0 = __half22float2(*(__half2*)&u0.x), q0 = __half22float2(*(__half2*)&u0.y);
            float2 p1 = __half22float2(*(__half2*)&u1.x), q1 = __half22float2(*(__half2*)&u1.y);
            float2 p2 = __half22float2(*(__half2*)&u2.x), q2 = __half22float2(*(__half2*)&u2.y);
            float2 p3 = __half22float2(*(__half2*)&u3.x), q3 = __half22float2(*(__half2*)&u3.y);
            acc.x = fmaf(p0.x, a0, fmaf(p1.x, a1, fmaf(p2.x, a2, fmaf(p3.x, a3, acc.x))));
            acc.y = fmaf(p0.y, a0, fmaf(p1.y, a1, fmaf(p2.y, a2, fmaf(p3.y, a3, acc.y))));
            acc.z = fmaf(q0.x, a0, fmaf(q1.x, a1, fmaf(q2.x, a2, fmaf(q3.x, a3, acc.z))));
            acc.w = fmaf(q0.y, a0, fmaf(q1.y, a1, fmaf(q2.y, a2, fmaf(q3.y, a3, acc.w))));
        }
        for (; t < deg; t++) {
            int src = s_src[w][t];
            float a = ((const float*)&s_al[w][t])[hsel];
            uint2 u = ((const uint2*)g_xw2h)[src * 32 + lane];
            float2 f0 = __half22float2(*(__half2*)&u.x);
            float2 f1 = __half22float2(*(__half2*)&u.y);
            acc.x = fmaf(f0.x, a, acc.x);
            acc.y = fmaf(f0.y, a, acc.y);
            acc.z = fmaf(f1.x, a, acc.z);
            acc.w = fmaf(f1.y, a, acc.w);
        }
        __syncwarp();
    } else {
        // general path
        float z0 = 0.f, z1 = 0.f, z2 = 0.f, z3 = 0.f;
        for (int j = start + lane; j < end; j += 32) {
            int src = g_csrc[j];
            float4 as = ((const float4*)g_asrc)[src];
            z0 += __expf(lrelu(as.x + ad.x));
            z1 += __expf(lrelu(as.y + ad.y));
            z2 += __expf(lrelu(as.z + ad.z));
            z3 += __expf(lrelu(as.w + ad.w));
        }
#pragma unroll
        for (int o = 16; o; o >>= 1) {
            z0 += __shfl_xor_sync(0xffffffffu, z0, o);
            z1 += __shfl_xor_sync(0xffffffffu, z1, o);
            z2 += __shfl_xor_sync(0xffffffffu, z2, o);
            z3 += __shfl_xor_sync(0xffffffffu, z3, o);
        }
        const float r0 = 1.f / z0, r1 = 1.f / z1, r2 = 1.f / z2, r3 = 1.f / z3;
        for (int j0 = start; j0 < end; j0 += 32) {
            int jj = j0 + lane;
            if (jj < end) {
                int src = g_csrc[jj];
                float4 as = ((const float4*)g_asrc)[src];
                float4 al;
                al.x = __expf(lrelu(as.x + ad.x)) * r0;
                al.y = __expf(lrelu(as.y + ad.y)) * r1;
                al.z = __expf(lrelu(as.z + ad.z)) * r2;
                al.w = __expf(lrelu(as.w + ad.w)) * r3;
                s_src[w][lane] = src;
                s_al[w][lane] = al;
            }
            __syncwarp();
            int cnt = min(32, end - j0);
            int t = 0;
            for (; t + 4 <= cnt; t += 4) {
                int s0 = s_src[w][t], s1 = s_src[w][t + 1];
                int s2 = s_src[w][t + 2], s3 = s_src[w][t + 3];
                float a0 = ((const float*)&s_al[w][t])[hsel];
                float a1 = ((const float*)&s_al[w][t + 1])[hsel];
                float a2 = ((const float*)&s_al[w][t + 2])[hsel];
                float a3 = ((const float*)&s_al[w][t + 3])[hsel];
                uint2 u0 = ((const uint2*)g_xw2h)[s0 * 32 + lane];
                uint2 u1 = ((const uint2*)g_xw2h)[s1 * 32 + lane];
                uint2 u2 = ((const uint2*)g_xw2h)[s2 * 32 + lane];
                uint2 u3 = ((const uint2*)g_xw2h)[s3 * 32 + lane];
                float2 p0 = __half22float2(*(__half2*)&u0.x), q0 = __half22float2(*(__half2*)&u0.y);
                float2 p1 = __half22float2(*(__half2*)&u1.x), q1 = __half22float2(*(__half2*)&u1.y);
                float2 p2 = __half22float2(*(__half2*)&u2.x), q2 = __half22float2(*(__half2*)&u2.y);
                float2 p3 = __half22float2(*(__half2*)&u3.x), q3 = __half22float2(*(__half2*)&u3.y);
                acc.x = fmaf(p0.x, a0, fmaf(p1.x, a1, fmaf(p2.x, a2, fmaf(p3.x, a3, acc.x))));
                acc.y = fmaf(p0.y, a0, fmaf(p1.y, a1, fmaf(p2.y, a2, fmaf(p3.y, a3, acc.y))));
                acc.z = fmaf(q0.x, a0, fmaf(q1.x, a1, fmaf(q2.x, a2, fmaf(q3.x, a3, acc.z))));
                acc.w = fmaf(q0.y, a0, fmaf(q1.y, a1, fmaf(q2.y, a2, fmaf(q3.y, a3, acc.w))));
            }
            for (; t < cnt; t++) {
                int src = s_src[w][t];
                float a = ((const float*)&s_al[w][t])[hsel];
                uint2 u = ((const uint2*)g_xw2h)[src * 32 + lane];
                float2 f0 = __half22float2(*(__half2*)&u.x);
                float2 f1 = __half22float2(*(__half2*)&u.y);
                acc.x = fmaf(f0.x, a, acc.x);
                acc.y = fmaf(f0.y, a, acc.y);
                acc.z = fmaf(f1.x, a, acc.z);
                acc.w = fmaf(f1.y, a, acc.w);
            }
            __syncwarp();
        }
    }

    // residual (fp16 hgcn) + LayerNorm + ReLU
    uint2 hr = ((const uint2*)g_hgcnh)[n * 32 + lane];
    float2 c0 = __half22float2(*(__half2*)&hr.x);
    float2 c1 = __half22float2(*(__half2*)&hr.y);
    acc.x += c0.x; acc.y += c0.y; acc.z += c1.x; acc.w += c1.y;
    float s = acc.x + acc.y + acc.z + acc.w;
#pragma unroll
    for (int o = 16; o; o >>= 1) s += __shfl_xor_sync(0xffffffffu, s, o);
    float mu = s * (1.0f / D);
    float dx = acc.x - mu, dy = acc.y - mu, dz = acc.z - mu, dw = acc.w - mu;
    float q = dx * dx + dy * dy + dz * dz + dw * dw;
#pragma unroll
    for (int o = 16; o; o >>= 1) q += __shfl_xor_sync(0xffffffffu, q, o);
    float rs = rsqrtf(q * (1.0f / D) + 1e-5f);
    float4 gg = ((const float4*)lg)[lane];
    float4 bb = ((const float4*)lb)[lane];
    float4 y;
    y.x = fmaxf(dx * rs * gg.x + bb.x, 0.f);
    y.y = fmaxf(dy * rs * gg.y + bb.y, 0.f);
    y.z = fmaxf(dz * rs * gg.z + bb.z, 0.f);
    y.w = fmaxf(dw * rs * gg.w + bb.w, 0.f);
    if (outf) {
        ((float4*)outf)[n * 32 + lane] = y;
    } else {
        uint2 hv;
        *(__half2*)&hv.x = __floats2half2_rn(y.x, y.y);
        *(__half2*)&hv.y = __floats2half2_rn(y.z, y.w);
        ((uint2*)outh)[n * 32 + lane] = hv;
    }
}

// ---------------- launch ----------------
extern "C" void kernel_launch(void* const* d_in, const int* in_sizes, int n_in,
                              void* d_out, int out_size) {
    const float* x      = (const float*)d_in[0];
    const int*   ei     = (const int*)  d_in[1];
    const float* gcn_w  = (const float*)d_in[2];
    const float* gcn_b  = (const float*)d_in[3];
    const float* gat_w  = (const float*)d_in[4];
    const float* att_s  = (const float*)d_in[5];
    const float* att_d  = (const float*)d_in[6];
    const float* gat_b  = (const float*)d_in[7];
    const float* ln_g   = (const float*)d_in[8];
    const float* ln_b   = (const float*)d_in[9];
    float* out = (float*)d_out;

    float  *p_dinv;
    __half *p_hh, *p_hgcnh, *p_xwh, *p_xw2h;
    cudaGetSymbolAddress((void**)&p_dinv,   g_dinv);
    cudaGetSymbolAddress((void**)&p_hh,     g_hh);
    cudaGetSymbolAddress((void**)&p_hgcnh,  g_hgcnh);
    cudaGetSymbolAddress((void**)&p_xwh,    g_xwh);
    cudaGetSymbolAddress((void**)&p_xw2h,   g_xw2h);

    const int T = 256;
    // CSR build (per replay; graph-capturable, no allocation).
    k_deg<<<cdiv(ETH, T), T>>>(ei);
    k_blockscan<<<NB, 256>>>();
    k_finalize<<<cdiv(NN, T), T>>>();
    k_fill<<<cdiv(ETH, T), T>>>(ei);
    // x -> fp16
    k_h2h<<<cdiv(NN * D / 8, T), T>>>(x);

    for (int l = 0; l < 3; l++) {
        // GCN (output pre-scaled by dinv[row])
        k_gemm<<<cdiv(NN, 128), T>>>(p_hh, gcn_w + l * D * D, p_xwh, NN, p_dinv,
                                     nullptr, nullptr);
        k_gcn_agg<<<cdiv(NN * 32, T), T>>>(gcn_b + l * D);
        // GAT (fused attention coefficients in epilogue)
        k_gemm<<<cdiv(NN, 128), T>>>(p_hgcnh, gat_w + l * D * D, p_xw2h, NN, nullptr,
                                     att_s + l * H * HD, att_d + l * H * HD);
        // GAT aggregation + residual + LN + ReLU fused
        if (l == 2)
            k_gat_ln<<<cdiv(NN * 32, T), T>>>(gat_b + l * D, ln_g + l * D, ln_b + l * D,
                                              out, nullptr);
        else
            k_gat_ln<<<cdiv(NN * 32, T), T>>>(gat_b + l * D, ln_g + l * D, ln_b + l * D,
                                              nullptr, p_hh);
    }
}